// round 1
// baseline (speedup 1.0000x reference)
#include <cuda_runtime.h>

// SimulatedRingDilatedAttention: per-position head-mixing attention.
// For each (b,n): S = Q[32,128] K^T /sqrt(128) -> [32,32]; P = softmax_g(S);
// O = P V -> [32,128]. 16384 independent positions.
//
// Design: 1 CTA (128 thr, 4 warps) per position. Warp w owns heads 8w..8w+7.
// Lane l owns scores column g=l for its 8 heads (K row read per-lane with
// chunk-rotation swizzle -> conflict-free). Softmax via warp shfl. Phase-2
// broadcasts P via shfl (no crossbar), V rows read as contiguous float4.
// All FMAs are packed fma.rn.f32x2 (2x fp32/instr, sm_103a).

constexpr int HEADS = 32;
constexpr int DIM   = 128;
constexpr int ROW4  = DIM / 4;           // 32 float4 chunks per row
constexpr int TILE4 = HEADS * ROW4;      // 1024 float4 per tile
constexpr int SMEM_BYTES = 3 * HEADS * DIM * 4;  // 48 KB

__device__ __forceinline__ unsigned long long pack2(float lo, float hi) {
    unsigned long long r;
    asm("mov.b64 %0, {%1, %2};" : "=l"(r) : "f"(lo), "f"(hi));
    return r;
}
__device__ __forceinline__ void unpack2(unsigned long long v, float& lo, float& hi) {
    asm("mov.b64 {%0, %1}, %2;" : "=f"(lo), "=f"(hi) : "l"(v));
}
__device__ __forceinline__ void fma2(unsigned long long& acc,
                                     unsigned long long a, unsigned long long b) {
    asm("fma.rn.f32x2 %0, %1, %2, %0;" : "+l"(acc) : "l"(a), "l"(b));
}
// chunk-rotation swizzle: rotate 16B chunks within groups of 8 by row index,
// so 32 lanes reading 32 distinct rows at equal chunk hit distinct bank groups.
__device__ __forceinline__ int swz(int row, int p) {
    return (p & ~7) | ((p + row) & 7);
}

__global__ void __launch_bounds__(128)
attn_kernel(const float* __restrict__ Q, const float* __restrict__ K,
            const float* __restrict__ V, float* __restrict__ O) {
    extern __shared__ float smem[];
    float4* Qs4 = reinterpret_cast<float4*>(smem);                 // plain [32][32]f4
    float4* Ks4 = reinterpret_cast<float4*>(smem + HEADS * DIM);   // swizzled
    float4* Vs4 = reinterpret_cast<float4*>(smem + 2 * HEADS * DIM); // swizzled

    const int pos = blockIdx.x;
    const long long base4 = (long long)pos * TILE4;
    const float4* Qg = reinterpret_cast<const float4*>(Q) + base4;
    const float4* Kg = reinterpret_cast<const float4*>(K) + base4;
    const float4* Vg = reinterpret_cast<const float4*>(V) + base4;

    const int tid = threadIdx.x;

    // ---- load tiles (coalesced float4, swizzled store for K/V) ----
    #pragma unroll
    for (int j = 0; j < 8; ++j) {
        int i = j * 128 + tid;
        int r = i >> 5, p = i & 31;
        Qs4[i] = Qg[i];
        Ks4[r * ROW4 + swz(r, p)] = Kg[i];
        Vs4[r * ROW4 + swz(r, p)] = Vg[i];
    }
    __syncthreads();

    const int lane = tid & 31;
    const int h0   = (tid >> 5) * 8;   // 8 heads per warp

    // ---- phase 1: scores. lane l computes S[h][g=l] for 8 heads ----
    unsigned long long acc[8];
    #pragma unroll
    for (int hh = 0; hh < 8; ++hh) acc[hh] = 0ULL;

    #pragma unroll 8
    for (int p = 0; p < 32; ++p) {
        float4 k4 = Ks4[lane * ROW4 + swz(lane, p)];   // K row = lane
        unsigned long long k2a = pack2(k4.x, k4.y);
        unsigned long long k2b = pack2(k4.z, k4.w);
        #pragma unroll
        for (int hh = 0; hh < 8; ++hh) {
            float4 q4 = Qs4[(h0 + hh) * ROW4 + p];     // broadcast
            fma2(acc[hh], pack2(q4.x, q4.y), k2a);
            fma2(acc[hh], pack2(q4.z, q4.w), k2b);
        }
    }

    // ---- softmax over g (across lanes), keep unnormalized e + 1/sum ----
    float e[8], rs[8];
    #pragma unroll
    for (int hh = 0; hh < 8; ++hh) {
        float lo, hi;
        unpack2(acc[hh], lo, hi);
        float s = (lo + hi) * 0.0883883476483184405f;  // 1/sqrt(128)
        float m = s;
        #pragma unroll
        for (int off = 16; off > 0; off >>= 1)
            m = fmaxf(m, __shfl_xor_sync(0xffffffffu, m, off));
        float ex = __expf(s - m);
        float sum = ex;
        #pragma unroll
        for (int off = 16; off > 0; off >>= 1)
            sum += __shfl_xor_sync(0xffffffffu, sum, off);
        e[hh]  = ex;
        rs[hh] = 1.0f / sum;
    }

    // ---- phase 2: O[h][4l..4l+3] = sum_g e[h][g] * V[g][:] (normalize at end) ----
    unsigned long long o0[8], o1[8];
    #pragma unroll
    for (int hh = 0; hh < 8; ++hh) { o0[hh] = 0ULL; o1[hh] = 0ULL; }

    #pragma unroll 4
    for (int g = 0; g < 32; ++g) {
        float4 v4 = Vs4[g * ROW4 + swz(g, lane)];      // row g, chunk = lane
        unsigned long long v2a = pack2(v4.x, v4.y);
        unsigned long long v2b = pack2(v4.z, v4.w);
        #pragma unroll
        for (int hh = 0; hh < 8; ++hh) {
            float pg = __shfl_sync(0xffffffffu, e[hh], g);
            unsigned long long p2 = pack2(pg, pg);
            fma2(o0[hh], p2, v2a);
            fma2(o1[hh], p2, v2b);
        }
    }

    // ---- epilogue: normalize + coalesced float4 store ----
    float4* Og = reinterpret_cast<float4*>(O) + base4;
    #pragma unroll
    for (int hh = 0; hh < 8; ++hh) {
        float a, b, c, d;
        unpack2(o0[hh], a, b);
        unpack2(o1[hh], c, d);
        float r0 = rs[hh];
        float4 r;
        r.x = a * r0; r.y = b * r0; r.z = c * r0; r.w = d * r0;
        Og[(h0 + hh) * ROW4 + lane] = r;
    }
}

extern "C" void kernel_launch(void* const* d_in, const int* in_sizes, int n_in,
                              void* d_out, int out_size) {
    const float* Q = (const float*)d_in[0];
    const float* K = (const float*)d_in[1];
    const float* V = (const float*)d_in[2];
    float* O = (float*)d_out;
    int positions = in_sizes[0] / (HEADS * DIM);   // B*N = 16384
    cudaFuncSetAttribute(attn_kernel,
                         cudaFuncAttributeMaxDynamicSharedMemorySize, SMEM_BYTES);
    attn_kernel<<<positions, 128, SMEM_BYTES>>>(Q, K, V, O);
}